// round 16
// baseline (speedup 1.0000x reference)
#include <cuda_runtime.h>
#include <cuda_bf16.h>
#include <cstdint>
#include <cstddef>

#define T_TOKENS 32768
#define K_DIM    1024
#define N_DIM    1024

// GEMM tiling (fp8 operands, m16n8k32 QMMA) — R11 best config, frozen
#define MT     128
#define NT     128
#define KB     128            // K bytes per pipeline stage
#define NKS    (K_DIM / KB)   // 8 stages
#define ATILE  (MT * KB)                // 16384 (128B rows, XOR-swizzled)
#define STAGE  (2 * ATILE)              // 32768
#define NSTG   3
#define SMEM_TOTAL (NSTG * STAGE)       // 98304 -> 2 CTAs/SM

#define SWZ(off) ((off) ^ (((off) >> 3) & 0x70))

// amax grid (R8-measured best shape)
#define AMAX_BLKS_IN 1024
#define AMAX_BLKS_W  64
#define AMAX_BLKS    (AMAX_BLKS_IN + AMAX_BLKS_W)

// fused kernel block layout: [W quant][A quant][GEMM]
#define W_QBLKS   256                   // 256 * 4096B = 1 MB
#define A_QBLKS   8192                  // 8192 * 4096B = 32 MB
#define GEMM_BLKS ((T_TOKENS / MT) * (N_DIM / NT))   // 2048
#define FUSED_BLKS (W_QBLKS + A_QBLKS + GEMM_BLKS)
#define N_MTILES  (T_TOKENS / MT)       // 256
#define QBLKS_PER_TILE 32               // 32 * 4096B = 128 rows

// ---------------- device scratch (static, allocation-free) ----------------
__device__ float g_blockmax[AMAX_BLKS];
__device__ float g_scales[3];                    // {s_in, s_w, comb}
__device__ unsigned int g_count;                 // amax completion counter (self-reset)
__device__ unsigned int g_w_rdy;                 // W quant done counter (self-reset)
__device__ unsigned int g_tile_rdy[N_MTILES];    // per-A-tile quant counters (self-reset)
__device__ unsigned int g_consumed[N_MTILES];    // per-tile consumer counters (self-reset)
__device__ unsigned int g_gemm_done;             // gemm CTA counter (self-reset)
__device__ __align__(16) unsigned char g_Aq[(size_t)T_TOKENS * K_DIM];  // 32 MB fp8
__device__ __align__(16) unsigned char g_Wq[(size_t)N_DIM   * K_DIM];   // 1 MB fp8

// ---------------- helpers ----------------
__device__ __forceinline__ uint32_t smem_u32(const void* p) {
    uint32_t a;
    asm("{ .reg .u64 t; cvta.to.shared.u64 t, %1; cvt.u32.u64 %0, t; }" : "=r"(a) : "l"(p));
    return a;
}

__device__ __forceinline__ void cp16(uint32_t dst, const void* src) {
    asm volatile("cp.async.cg.shared.global [%0], [%1], 16;" :: "r"(dst), "l"(src));
}
#define CP_COMMIT()  asm volatile("cp.async.commit_group;" ::: "memory")
#define CP_WAIT1()   asm volatile("cp.async.wait_group 1;" ::: "memory")
#define CP_WAIT0()   asm volatile("cp.async.wait_group 0;" ::: "memory")

__device__ __forceinline__ void ldm_x4(uint32_t* r, uint32_t addr) {
    asm volatile("ldmatrix.sync.aligned.m8n8.x4.shared.b16 {%0,%1,%2,%3}, [%4];"
                 : "=r"(r[0]), "=r"(r[1]), "=r"(r[2]), "=r"(r[3]) : "r"(addr));
}

__device__ __forceinline__ void mma_f8(float* c, const uint32_t* a, uint32_t b0, uint32_t b1) {
    asm volatile("mma.sync.aligned.m16n8k32.row.col.f32.e4m3.e4m3.f32 "
                 "{%0,%1,%2,%3}, {%4,%5,%6,%7}, {%8,%9}, {%0,%1,%2,%3};"
                 : "+f"(c[0]), "+f"(c[1]), "+f"(c[2]), "+f"(c[3])
                 : "r"(a[0]), "r"(a[1]), "r"(a[2]), "r"(a[3]), "r"(b0), "r"(b1));
}

__device__ __forceinline__ float block_reduce_max(float v) {
    __shared__ float s[32];
    int lane = threadIdx.x & 31, wid = threadIdx.x >> 5;
    __syncthreads();                                // safe for consecutive calls
    #pragma unroll
    for (int o = 16; o; o >>= 1) v = fmaxf(v, __shfl_xor_sync(0xffffffffu, v, o));
    if (lane == 0) s[wid] = v;
    __syncthreads();
    if (wid == 0) {
        v = (lane < (int)(blockDim.x >> 5)) ? s[lane] : 0.0f;
        #pragma unroll
        for (int o = 16; o; o >>= 1) v = fmaxf(v, __shfl_xor_sync(0xffffffffu, v, o));
        if (lane == 0) s[0] = v;
    }
    __syncthreads();
    return s[0];
}

__device__ __forceinline__ float scale_from_amax(float amax) {
    return fminf(__fdiv_rn(448.0f, fmaxf(amax, 1e-12f)), 448.0f);
}

__device__ __forceinline__ unsigned short fp8x2(float lo, float hi) {
    unsigned short r;
    asm("cvt.rn.satfinite.e4m3x2.f32 %0, %1, %2;" : "=h"(r) : "f"(hi), "f"(lo));
    return r;
}

// quantize 64B of fp32 -> 16B fp8 (one uint4 per thread-index)
__device__ __forceinline__ void quant16(const float4* __restrict__ x, uint4* __restrict__ y,
                                        int i, float s) {
    unsigned int w[4];
    #pragma unroll
    for (int q = 0; q < 4; q++) {
        float4 v = x[i * 4 + q];
        unsigned short l16 = fp8x2(__fmul_rn(v.x, s), __fmul_rn(v.y, s));
        unsigned short h16 = fp8x2(__fmul_rn(v.z, s), __fmul_rn(v.w, s));
        w[q] = (unsigned)l16 | ((unsigned)h16 << 16);
    }
    uint4 o; o.x = w[0]; o.y = w[1]; o.z = w[2]; o.w = w[3];
    y[i] = o;
}

// ---------------- pass 1: merged amax + last-block scale finalize ----------------
__global__ void amax2_kernel(const float4* __restrict__ xin, int n_in4,
                             const float4* __restrict__ xw,  int n_w4) {
    int n4, bid, nblk;
    const float4* x;
    if (blockIdx.x < AMAX_BLKS_IN) {
        x = xin; n4 = n_in4; bid = blockIdx.x; nblk = AMAX_BLKS_IN;
    } else {
        x = xw;  n4 = n_w4;  bid = blockIdx.x - AMAX_BLKS_IN; nblk = AMAX_BLKS_W;
    }
    int stride = nblk * blockDim.x;
    int i = bid * blockDim.x + threadIdx.x;
    float m0 = 0.0f, m1 = 0.0f, m2 = 0.0f, m3 = 0.0f;
    for (; i + 3 * stride < n4; i += 4 * stride) {
        float4 a = x[i];
        float4 b = x[i + stride];
        float4 c = x[i + 2 * stride];
        float4 d = x[i + 3 * stride];
        m0 = fmaxf(m0, fmaxf(fmaxf(fabsf(a.x), fabsf(a.y)), fmaxf(fabsf(a.z), fabsf(a.w))));
        m1 = fmaxf(m1, fmaxf(fmaxf(fabsf(b.x), fabsf(b.y)), fmaxf(fabsf(b.z), fabsf(b.w))));
        m2 = fmaxf(m2, fmaxf(fmaxf(fabsf(c.x), fabsf(c.y)), fmaxf(fabsf(c.z), fabsf(c.w))));
        m3 = fmaxf(m3, fmaxf(fmaxf(fabsf(d.x), fabsf(d.y)), fmaxf(fabsf(d.z), fabsf(d.w))));
    }
    for (; i < n4; i += stride) {
        float4 a = x[i];
        m0 = fmaxf(m0, fmaxf(fmaxf(fabsf(a.x), fabsf(a.y)), fmaxf(fabsf(a.z), fabsf(a.w))));
    }
    float m = block_reduce_max(fmaxf(fmaxf(m0, m1), fmaxf(m2, m3)));

    __shared__ bool is_last;
    if (threadIdx.x == 0) {
        g_blockmax[blockIdx.x] = m;
        __threadfence();
        unsigned int done = atomicAdd(&g_count, 1u);
        is_last = (done == AMAX_BLKS - 1);
    }
    __syncthreads();

    if (is_last) {
        float mi = 0.0f;
        for (int t = threadIdx.x; t < AMAX_BLKS_IN; t += blockDim.x)
            mi = fmaxf(mi, g_blockmax[t]);
        float amax_in = block_reduce_max(mi);
        float mw = (threadIdx.x < AMAX_BLKS_W) ? g_blockmax[AMAX_BLKS_IN + threadIdx.x] : 0.0f;
        float amax_w = block_reduce_max(mw);
        if (threadIdx.x == 0) {
            float s_in = scale_from_amax(amax_in);
            float s_w  = scale_from_amax(amax_w);
            g_scales[0] = s_in;
            g_scales[1] = s_w;
            g_scales[2] = __fmul_rn(__frcp_rn(s_in), __frcp_rn(s_w));
            g_count = 0;
        }
    }
}

// ---------------- pass 2: FUSED quant + GEMM (producer/consumer, one launch) ----------------
__device__ __forceinline__ void load_stage(uint32_t sb, int buf, int mt, int nt, int ks, int tid) {
    uint32_t sa = sb + buf * STAGE;
    const unsigned char* ag = g_Aq + ((size_t)mt * MT) * K_DIM + ks * KB;
    #pragma unroll
    for (int i = 0; i < 4; i++) {
        int id = tid + i * 256;
        int r = id & 127, c = id >> 7;
        uint32_t off = (uint32_t)(r * 128 + c * 16);
        cp16(sa + SWZ(off), ag + (size_t)r * K_DIM + c * 16);
    }
    uint32_t sbb = sa + ATILE;
    const unsigned char* bg = g_Wq + ((size_t)nt * NT) * K_DIM + ks * KB;
    #pragma unroll
    for (int i = 0; i < 4; i++) {
        int id = tid + i * 256;
        int r = id & 127, c = id >> 7;
        uint32_t off = (uint32_t)(r * 128 + c * 16);
        cp16(sbb + SWZ(off), bg + (size_t)r * K_DIM + c * 16);
    }
}

__global__ void __launch_bounds__(256, 2)
fused_kernel(const float4* __restrict__ xin, const float4* __restrict__ xw,
             float* __restrict__ out, const float* __restrict__ bias) {
    int tid = threadIdx.x;
    int bid = blockIdx.x;

    // ---- W quant producers (bids [0, W_QBLKS)) ----
    if (bid < W_QBLKS) {
        quant16(xw, (uint4*)g_Wq, bid * 256 + tid, g_scales[1]);
        __threadfence();                               // publish before counting
        __syncthreads();
        if (tid == 0) atomicAdd(&g_w_rdy, 1u);
        return;
    }
    bid -= W_QBLKS;

    // ---- A quant producers (bids [W_QBLKS, W_QBLKS+A_QBLKS)) ----
    if (bid < A_QBLKS) {
        quant16(xin, (uint4*)g_Aq, bid * 256 + tid, g_scales[0]);
        __threadfence();
        __syncthreads();
        if (tid == 0) atomicAdd(&g_tile_rdy[bid >> 5], 1u);   // 32 blocks per 128-row tile
        return;
    }
    bid -= A_QBLKS;

    // ---- GEMM consumers ----
    extern __shared__ char smem[];
    uint32_t sb = smem_u32(smem);
    int lane = tid & 31;
    int w    = tid >> 5;
    int wm   = w & 3;
    int wn   = w >> 2;
    int nt   = bid & 7;
    int mt   = bid >> 3;

    // wait for W fully quantized and this CTA's A tile quantized
    if (tid == 0) {
        while (*((volatile unsigned int*)&g_w_rdy) < W_QBLKS) __nanosleep(64);
        while (*((volatile unsigned int*)&g_tile_rdy[mt]) < QBLKS_PER_TILE) __nanosleep(64);
    }
    __syncthreads();   // threadFenceReduction idiom: writer fence + atomic + CTA barrier

    float acc[2][8][4];
    #pragma unroll
    for (int mf = 0; mf < 2; mf++)
        #pragma unroll
        for (int nf = 0; nf < 8; nf++)
            #pragma unroll
            for (int j = 0; j < 4; j++) acc[mf][nf][j] = 0.0f;

    load_stage(sb, 0, mt, nt, 0, tid); CP_COMMIT();
    load_stage(sb, 1, mt, nt, 1, tid); CP_COMMIT();

    float comb = g_scales[2];

    uint32_t a_row = (uint32_t)(wm * 32 + (lane & 15));
    uint32_t b_row = (uint32_t)(wn * 64 + (lane & 15));
    uint32_t klane = (uint32_t)(lane & 16);

    #pragma unroll 1
    for (int ks = 0; ks < NKS; ks++) {
        if (ks == NKS - 1) { CP_WAIT0(); } else { CP_WAIT1(); }
        __syncthreads();

        int buf = ks % NSTG;
        uint32_t abase = sb + buf * STAGE;
        uint32_t bbase = abase + ATILE;

        #pragma unroll
        for (int kk = 0; kk < 4; kk++) {
            uint32_t kb = (uint32_t)(kk * 32) + klane;
            uint32_t afr[2][4];
            {
                uint32_t o0 = (a_row +  0) * 128 + kb;
                uint32_t o1 = (a_row + 16) * 128 + kb;
                ldm_x4(afr[0], abase + SWZ(o0));
                ldm_x4(afr[1], abase + SWZ(o1));
            }
            uint32_t bfr[4][4];
            #pragma unroll
            for (int p = 0; p < 4; p++) {
                uint32_t ob = (b_row + p * 16) * 128 + kb;
                ldm_x4(bfr[p], bbase + SWZ(ob));
            }
            #pragma unroll
            for (int mf = 0; mf < 2; mf++)
                #pragma unroll
                for (int nf = 0; nf < 8; nf++) {
                    int p = nf >> 1, sel = nf & 1;
                    mma_f8(acc[mf][nf], afr[mf], bfr[p][sel], bfr[p][sel + 2]);
                }
        }

        if (ks + 2 < NKS) {
            load_stage(sb, (ks + 2) % NSTG, mt, nt, ks + 2, tid);
            CP_COMMIT();
        }
    }

    // epilogue: dequant + bias + bf16 round, direct stores
    int colb = nt * NT + wn * 64 + (lane & 3) * 2;
    float2 bv[8];
    #pragma unroll
    for (int nf = 0; nf < 8; nf++) {
        bv[nf].x = bias[colb + nf * 8 + 0];
        bv[nf].y = bias[colb + nf * 8 + 1];
    }

    int row0 = mt * MT + wm * 32 + (lane >> 2);
    #pragma unroll
    for (int mf = 0; mf < 2; mf++) {
        #pragma unroll
        for (int h = 0; h < 2; h++) {
            int row = row0 + mf * 16 + h * 8;
            float* orow = out + (size_t)row * N_DIM + colb;
            #pragma unroll
            for (int nf = 0; nf < 8; nf++) {
                float v0 = __fadd_rn(__fmul_rn(acc[mf][nf][h * 2 + 0], comb), bv[nf].x);
                float v1 = __fadd_rn(__fmul_rn(acc[mf][nf][h * 2 + 1], comb), bv[nf].y);
                float2 o;
                o.x = __bfloat162float(__float2bfloat16(v0));
                o.y = __bfloat162float(__float2bfloat16(v1));
                *reinterpret_cast<float2*>(orow + nf * 8) = o;
            }
        }
    }

    // self-reset counters for deterministic graph replays
    __syncthreads();
    if (tid == 0) {
        unsigned int c = atomicAdd(&g_consumed[mt], 1u);
        if (c == 7u) { g_tile_rdy[mt] = 0u; g_consumed[mt] = 0u; }   // last of 8 nt consumers
        unsigned int d = atomicAdd(&g_gemm_done, 1u);
        if (d == GEMM_BLKS - 1u) { g_w_rdy = 0u; g_gemm_done = 0u; } // last gemm CTA
    }
}

// ---------------- host launcher ----------------
extern "C" void kernel_launch(void* const* d_in, const int* in_sizes, int n_in,
                              void* d_out, int out_size) {
    const float* input  = (const float*)d_in[0];   // [4, 8192, 1024] f32
    const float* weight = (const float*)d_in[1];   // [1024, 1024]   f32
    const float* bias   = (const float*)d_in[2];   // [1024]         f32
    float* out = (float*)d_out;

    cudaFuncSetAttribute(fused_kernel, cudaFuncAttributeMaxDynamicSharedMemorySize, SMEM_TOTAL);

    amax2_kernel<<<AMAX_BLKS, 256>>>(
        (const float4*)input,  (T_TOKENS * K_DIM) / 4,
        (const float4*)weight, (N_DIM    * K_DIM) / 4);

    fused_kernel<<<FUSED_BLKS, 256, SMEM_TOTAL>>>(
        (const float4*)input, (const float4*)weight, out, bias);
}

// round 17
// speedup vs baseline: 1.1465x; 1.1465x over previous
#include <cuda_runtime.h>
#include <cuda_bf16.h>
#include <cstdint>
#include <cstddef>

#define T_TOKENS 32768
#define K_DIM    1024
#define N_DIM    1024

// GEMM tiling (fp8 operands, m16n8k32 QMMA) — R11 best config, frozen
#define MT     128
#define NT     128
#define KB     128            // K bytes per pipeline stage
#define NKS    (K_DIM / KB)   // 8 stages
#define ATILE  (MT * KB)                // 16384 (128B rows, XOR-swizzled)
#define STAGE  (2 * ATILE)              // 32768
#define NSTG   3
#define SMEM_TOTAL (NSTG * STAGE)       // 98304 -> 2 CTAs/SM

#define SWZ(off) ((off) ^ (((off) >> 3) & 0x70))

// amax grid (R8/R14-measured best shape: 1024+64)
#define AMAX_BLKS_IN 1024
#define AMAX_BLKS_W  64
#define AMAX_BLKS    (AMAX_BLKS_IN + AMAX_BLKS_W)
#define QUANT_BLKS_IN 8192              // (32768*1024/16)/256
#define QUANT_BLKS_W  256               // (1024*1024/16)/256

// ---------------- device scratch (static, allocation-free) ----------------
__device__ float g_blockmax[AMAX_BLKS];          // per-block amax (every slot rewritten each run)
__device__ float g_scales[3];                    // {s_in, s_w, comb} — written by last amax block
__device__ unsigned int g_count;                 // completion counter (self-reset by last block)
__device__ __align__(16) unsigned char g_Aq[(size_t)T_TOKENS * K_DIM];  // 32 MB fp8
__device__ __align__(16) unsigned char g_Wq[(size_t)N_DIM   * K_DIM];   // 1 MB fp8

// ---------------- helpers ----------------
__device__ __forceinline__ uint32_t smem_u32(const void* p) {
    uint32_t a;
    asm("{ .reg .u64 t; cvta.to.shared.u64 t, %1; cvt.u32.u64 %0, t; }" : "=r"(a) : "l"(p));
    return a;
}

__device__ __forceinline__ void cp16(uint32_t dst, const void* src) {
    asm volatile("cp.async.cg.shared.global [%0], [%1], 16;" :: "r"(dst), "l"(src));
}
#define CP_COMMIT()  asm volatile("cp.async.commit_group;" ::: "memory")
#define CP_WAIT1()   asm volatile("cp.async.wait_group 1;" ::: "memory")
#define CP_WAIT0()   asm volatile("cp.async.wait_group 0;" ::: "memory")

__device__ __forceinline__ void ldm_x4(uint32_t* r, uint32_t addr) {
    asm volatile("ldmatrix.sync.aligned.m8n8.x4.shared.b16 {%0,%1,%2,%3}, [%4];"
                 : "=r"(r[0]), "=r"(r[1]), "=r"(r[2]), "=r"(r[3]) : "r"(addr));
}

__device__ __forceinline__ void mma_f8(float* c, const uint32_t* a, uint32_t b0, uint32_t b1) {
    asm volatile("mma.sync.aligned.m16n8k32.row.col.f32.e4m3.e4m3.f32 "
                 "{%0,%1,%2,%3}, {%4,%5,%6,%7}, {%8,%9}, {%0,%1,%2,%3};"
                 : "+f"(c[0]), "+f"(c[1]), "+f"(c[2]), "+f"(c[3])
                 : "r"(a[0]), "r"(a[1]), "r"(a[2]), "r"(a[3]), "r"(b0), "r"(b1));
}

// block-wide max; entry barrier makes consecutive calls safe (smem buffer reuse)
__device__ __forceinline__ float block_reduce_max(float v) {
    __shared__ float s[32];
    int lane = threadIdx.x & 31, wid = threadIdx.x >> 5;
    __syncthreads();
    #pragma unroll
    for (int o = 16; o; o >>= 1) v = fmaxf(v, __shfl_xor_sync(0xffffffffu, v, o));
    if (lane == 0) s[wid] = v;
    __syncthreads();
    if (wid == 0) {
        v = (lane < (int)(blockDim.x >> 5)) ? s[lane] : 0.0f;
        #pragma unroll
        for (int o = 16; o; o >>= 1) v = fmaxf(v, __shfl_xor_sync(0xffffffffu, v, o));
        if (lane == 0) s[0] = v;
    }
    __syncthreads();
    return s[0];
}

// scale = min(448 / max(amax, 1e-12), 448) with IEEE RN ops (matches reference exactly)
__device__ __forceinline__ float scale_from_amax(float amax) {
    return fminf(__fdiv_rn(448.0f, fmaxf(amax, 1e-12f)), 448.0f);
}

__device__ __forceinline__ unsigned short fp8x2(float lo, float hi) {
    unsigned short r;
    asm("cvt.rn.satfinite.e4m3x2.f32 %0, %1, %2;" : "=h"(r) : "f"(hi), "f"(lo));
    return r;
}

// ---------------- pass 1: merged amax + last-block scale finalize ----------------
__global__ void amax2_kernel(const float4* __restrict__ xin, int n_in4,
                             const float4* __restrict__ xw,  int n_w4) {
    int n4, bid, nblk;
    const float4* x;
    if (blockIdx.x < AMAX_BLKS_IN) {
        x = xin; n4 = n_in4; bid = blockIdx.x; nblk = AMAX_BLKS_IN;
    } else {
        x = xw;  n4 = n_w4;  bid = blockIdx.x - AMAX_BLKS_IN; nblk = AMAX_BLKS_W;
    }
    int stride = nblk * blockDim.x;
    int i = bid * blockDim.x + threadIdx.x;
    float m0 = 0.0f, m1 = 0.0f, m2 = 0.0f, m3 = 0.0f;   // ILP-4
    for (; i + 3 * stride < n4; i += 4 * stride) {
        float4 a = x[i];
        float4 b = x[i + stride];
        float4 c = x[i + 2 * stride];
        float4 d = x[i + 3 * stride];
        m0 = fmaxf(m0, fmaxf(fmaxf(fabsf(a.x), fabsf(a.y)), fmaxf(fabsf(a.z), fabsf(a.w))));
        m1 = fmaxf(m1, fmaxf(fmaxf(fabsf(b.x), fabsf(b.y)), fmaxf(fabsf(b.z), fabsf(b.w))));
        m2 = fmaxf(m2, fmaxf(fmaxf(fabsf(c.x), fabsf(c.y)), fmaxf(fabsf(c.z), fabsf(c.w))));
        m3 = fmaxf(m3, fmaxf(fmaxf(fabsf(d.x), fabsf(d.y)), fmaxf(fabsf(d.z), fabsf(d.w))));
    }
    for (; i < n4; i += stride) {
        float4 a = x[i];
        m0 = fmaxf(m0, fmaxf(fmaxf(fabsf(a.x), fabsf(a.y)), fmaxf(fabsf(a.z), fabsf(a.w))));
    }
    float m = block_reduce_max(fmaxf(fmaxf(m0, m1), fmaxf(m2, m3)));

    __shared__ bool is_last;
    if (threadIdx.x == 0) {
        g_blockmax[blockIdx.x] = m;
        __threadfence();                                  // publish blockmax before counting
        unsigned int done = atomicAdd(&g_count, 1u);
        is_last = (done == AMAX_BLKS - 1);
    }
    __syncthreads();

    if (is_last) {                                        // one block finalizes the scales
        float mi = 0.0f;
        for (int t = threadIdx.x; t < AMAX_BLKS_IN; t += blockDim.x)
            mi = fmaxf(mi, g_blockmax[t]);
        float amax_in = block_reduce_max(mi);
        float mw = (threadIdx.x < AMAX_BLKS_W) ? g_blockmax[AMAX_BLKS_IN + threadIdx.x] : 0.0f;
        float amax_w = block_reduce_max(mw);
        if (threadIdx.x == 0) {
            float s_in = scale_from_amax(amax_in);
            float s_w  = scale_from_amax(amax_w);
            g_scales[0] = s_in;
            g_scales[1] = s_w;
            g_scales[2] = __fmul_rn(__frcp_rn(s_in), __frcp_rn(s_w));
            g_count = 0;                                  // reset for next graph replay
        }
    }
}

// ---------------- pass 2: merged quantize (scalar scale read) ----------------
__global__ void quant2_kernel(const float4* __restrict__ xin, int n_in16,
                              const float4* __restrict__ xw,  int n_w16) {
    int which, n16, i;
    const float4* x;
    uint4* y;
    if (blockIdx.x < QUANT_BLKS_IN) {
        which = 0; x = xin; n16 = n_in16; y = (uint4*)g_Aq;
        i = blockIdx.x * blockDim.x + threadIdx.x;
    } else {
        which = 1; x = xw;  n16 = n_w16;  y = (uint4*)g_Wq;
        i = (blockIdx.x - QUANT_BLKS_IN) * blockDim.x + threadIdx.x;
    }
    if (i >= n16) return;
    float s = g_scales[which];                            // broadcast scalar
    unsigned int w[4];
    #pragma unroll
    for (int q = 0; q < 4; q++) {
        float4 v = x[i * 4 + q];
        unsigned short l16 = fp8x2(__fmul_rn(v.x, s), __fmul_rn(v.y, s));
        unsigned short h16 = fp8x2(__fmul_rn(v.z, s), __fmul_rn(v.w, s));
        w[q] = (unsigned)l16 | ((unsigned)h16 << 16);
    }
    uint4 o; o.x = w[0]; o.y = w[1]; o.z = w[2]; o.w = w[3];
    y[i] = o;
}

// ---------------- pass 3: fp8 GEMM (R11 frozen config) ----------------
__device__ __forceinline__ void load_stage(uint32_t sb, int buf, int mt, int nt, int ks, int tid) {
    uint32_t sa = sb + buf * STAGE;
    const unsigned char* ag = g_Aq + ((size_t)mt * MT) * K_DIM + ks * KB;
    #pragma unroll
    for (int i = 0; i < 4; i++) {
        int id = tid + i * 256;
        int r = id & 127, c = id >> 7;
        uint32_t off = (uint32_t)(r * 128 + c * 16);
        cp16(sa + SWZ(off), ag + (size_t)r * K_DIM + c * 16);
    }
    uint32_t sbb = sa + ATILE;
    const unsigned char* bg = g_Wq + ((size_t)nt * NT) * K_DIM + ks * KB;
    #pragma unroll
    for (int i = 0; i < 4; i++) {
        int id = tid + i * 256;
        int r = id & 127, c = id >> 7;
        uint32_t off = (uint32_t)(r * 128 + c * 16);
        cp16(sbb + SWZ(off), bg + (size_t)r * K_DIM + c * 16);
    }
}

__global__ void __launch_bounds__(256, 2)
gemm_kernel(float* __restrict__ out, const float* __restrict__ bias) {
    extern __shared__ char smem[];
    uint32_t sb = smem_u32(smem);
    int tid  = threadIdx.x;
    int lane = tid & 31;
    int w    = tid >> 5;
    int wm   = w & 3;          // 4 warps in M
    int wn   = w >> 2;         // 2 warps in N
    int nt   = blockIdx.x & 7;     // 8 N tiles
    int mt   = blockIdx.x >> 3;    // 256 M tiles (nt inner -> A tile L2 reuse)

    float acc[2][8][4];
    #pragma unroll
    for (int mf = 0; mf < 2; mf++)
        #pragma unroll
        for (int nf = 0; nf < 8; nf++)
            #pragma unroll
            for (int j = 0; j < 4; j++) acc[mf][nf][j] = 0.0f;

    // prologue: stages 0, 1
    load_stage(sb, 0, mt, nt, 0, tid); CP_COMMIT();
    load_stage(sb, 1, mt, nt, 1, tid); CP_COMMIT();

    float comb = g_scales[2];                             // uniform broadcast load

    uint32_t a_row = (uint32_t)(wm * 32 + (lane & 15));
    uint32_t b_row = (uint32_t)(wn * 64 + (lane & 15));
    uint32_t klane = (uint32_t)(lane & 16);

    #pragma unroll 1
    for (int ks = 0; ks < NKS; ks++) {
        if (ks == NKS - 1) { CP_WAIT0(); } else { CP_WAIT1(); }
        __syncthreads();

        int buf = ks % NSTG;
        uint32_t abase = sb + buf * STAGE;
        uint32_t bbase = abase + ATILE;

        #pragma unroll
        for (int kk = 0; kk < 4; kk++) {          // 4 x k32 slabs per 128B stage
            uint32_t kb = (uint32_t)(kk * 32) + klane;
            uint32_t afr[2][4];
            {
                uint32_t o0 = (a_row +  0) * 128 + kb;
                uint32_t o1 = (a_row + 16) * 128 + kb;
                ldm_x4(afr[0], abase + SWZ(o0));
                ldm_x4(afr[1], abase + SWZ(o1));
            }
            uint32_t bfr[4][4];
            #pragma unroll
            for (int p = 0; p < 4; p++) {
                uint32_t ob = (b_row + p * 16) * 128 + kb;
                ldm_x4(bfr[p], bbase + SWZ(ob));
            }
            #pragma unroll
            for (int mf = 0; mf < 2; mf++)
                #pragma unroll
                for (int nf = 0; nf < 8; nf++) {
                    int p = nf >> 1, sel = nf & 1;
                    mma_f8(acc[mf][nf], afr[mf], bfr[p][sel], bfr[p][sel + 2]);
                }
        }

        if (ks + 2 < NKS) {   // refill buffer consumed two iterations ago
            load_stage(sb, (ks + 2) % NSTG, mt, nt, ks + 2, tid);
            CP_COMMIT();
        }
    }

    // ---------------- epilogue: dequant + bias + bf16 round, direct stores ----------------
    int colb = nt * NT + wn * 64 + (lane & 3) * 2;
    float2 bv[8];
    #pragma unroll
    for (int nf = 0; nf < 8; nf++) {
        bv[nf].x = bias[colb + nf * 8 + 0];
        bv[nf].y = bias[colb + nf * 8 + 1];
    }

    int row0 = mt * MT + wm * 32 + (lane >> 2);
    #pragma unroll
    for (int mf = 0; mf < 2; mf++) {
        #pragma unroll
        for (int h = 0; h < 2; h++) {
            int row = row0 + mf * 16 + h * 8;
            float* orow = out + (size_t)row * N_DIM + colb;
            #pragma unroll
            for (int nf = 0; nf < 8; nf++) {
                float v0 = __fadd_rn(__fmul_rn(acc[mf][nf][h * 2 + 0], comb), bv[nf].x);
                float v1 = __fadd_rn(__fmul_rn(acc[mf][nf][h * 2 + 1], comb), bv[nf].y);
                float2 o;
                o.x = __bfloat162float(__float2bfloat16(v0));
                o.y = __bfloat162float(__float2bfloat16(v1));
                *reinterpret_cast<float2*>(orow + nf * 8) = o;
            }
        }
    }
}

// ---------------- host launcher ----------------
extern "C" void kernel_launch(void* const* d_in, const int* in_sizes, int n_in,
                              void* d_out, int out_size) {
    const float* input  = (const float*)d_in[0];   // [4, 8192, 1024] f32
    const float* weight = (const float*)d_in[1];   // [1024, 1024]   f32
    const float* bias   = (const float*)d_in[2];   // [1024]         f32
    float* out = (float*)d_out;

    cudaFuncSetAttribute(gemm_kernel, cudaFuncAttributeMaxDynamicSharedMemorySize, SMEM_TOTAL);

    amax2_kernel<<<AMAX_BLKS, 256>>>(
        (const float4*)input,  (T_TOKENS * K_DIM) / 4,
        (const float4*)weight, (N_DIM    * K_DIM) / 4);

    quant2_kernel<<<QUANT_BLKS_IN + QUANT_BLKS_W, 256>>>(
        (const float4*)input,  (T_TOKENS * K_DIM) / 16,
        (const float4*)weight, (N_DIM    * K_DIM) / 16);

    int grid = (T_TOKENS / MT) * (N_DIM / NT);   // 256 * 8 = 2048 CTAs
    gemm_kernel<<<grid, 256, SMEM_TOTAL>>>(out, bias);
}